// round 4
// baseline (speedup 1.0000x reference)
#include <cuda_runtime.h>
#include <cstdint>

// Conv2D 3x3 SAME stride-1 via mma.sync.m16n8k8.tf32 implicit GEMM.
// x [16,128,128,64] NHWC fp32, w [3,3,64,128] HWIO, bias [128] -> out [16,128,128,128] fp32.
// CTA tile: M=128 (2 output rows x 64-pixel strip) x N=128 couts.
// 8 warps, warp tile 32x64, acc=64 regs -> 2 CTAs/SM so staging/sync bubbles
// of one CTA hide under the peer CTA's tensor work.

#define CH 128
#define CW 128
#define CIN 64
#define COUT 128

#define AP 68                    // plane row stride (words): conflict-free frags
#define A_PLANE (66 * AP)        // 66 pixel rows (64 + 2 halo) x 68
#define AS_WORDS (4 * A_PLANE)   // 4 input-row planes
#define BP 68
#define BS_WORDS (COUT * BP)     // single-buffered weight tap
#define SMEM_BYTES ((AS_WORDS + BS_WORDS) * 4)   // 106,624 B -> 2 CTAs/SM

static __device__ __forceinline__ uint32_t cvt_tf32(float f) {
    uint32_t r; asm("cvt.rna.tf32.f32 %0, %1;" : "=r"(r) : "f"(f)); return r;
}

#define MMA_TF32(c, a, b0, b1) \
    asm volatile("mma.sync.aligned.m16n8k8.row.col.f32.tf32.tf32.f32 " \
        "{%0,%1,%2,%3}, {%4,%5,%6,%7}, {%8,%9}, {%0,%1,%2,%3};" \
        : "+f"((c)[0]), "+f"((c)[1]), "+f"((c)[2]), "+f"((c)[3]) \
        : "r"((a)[0]), "r"((a)[1]), "r"((a)[2]), "r"((a)[3]), \
          "r"(b0), "r"(b1))

__global__ __launch_bounds__(256, 2)
void conv3x3_mma2_kernel(const float* __restrict__ x,
                         const float* __restrict__ wt,
                         const float* __restrict__ bias,
                         float* __restrict__ out) {
    extern __shared__ uint32_t smem[];
    uint32_t* As = smem;                 // [plane 0..3][pixrow 0..65][cin 0..63]
    uint32_t* Bs = smem + AS_WORDS;      // [cout][cin]

    const int tid  = threadIdx.x;
    const int wid  = tid >> 5;
    const int lane = tid & 31;
    const int gid  = lane >> 2;          // 0..7
    const int t4   = lane & 3;           // 0..3

    const int warp_m = wid >> 1;         // 0..3
    const int warp_n = wid & 1;          // 0..1

    const int bx = blockIdx.x;
    const int n  = bx >> 7;
    const int r  = bx & 127;
    const int h0 = (r >> 1) << 1;        // output rows h0, h0+1
    const int ps = (r & 1) << 6;         // pixel strip base: 0 or 64

    // ---- stage A: 4 input row planes (h0-1..h0+2), 66 pixels with halo ----
    const float* xn = x + (size_t)n * CH * CW * CIN;
#pragma unroll
    for (int r4 = 0; r4 < 4; ++r4) {
        const int hr = h0 - 1 + r4;
        uint32_t* plane = As + r4 * A_PLANE;
        if ((unsigned)hr < (unsigned)CH) {
            const float* xrow = xn + (size_t)hr * CW * CIN;
#pragma unroll
            for (int i = 0; i < 5; ++i) {
                const int f4 = i * 256 + tid;            // 0..1055
                if (f4 < 66 * 16) {
                    const int pr = f4 >> 4;              // plane pixel row
                    const int c4 = (f4 & 15) << 2;
                    const int gp = ps - 1 + pr;          // global pixel
                    uint4 tv = make_uint4(0u, 0u, 0u, 0u);
                    if ((unsigned)gp < (unsigned)CW) {
                        const float4 v = *(const float4*)&xrow[gp * CIN + c4];
                        tv.x = cvt_tf32(v.x); tv.y = cvt_tf32(v.y);
                        tv.z = cvt_tf32(v.z); tv.w = cvt_tf32(v.w);
                    }
                    *(uint4*)&plane[pr * AP + c4] = tv;
                }
            }
        } else {
            for (int i = tid; i < A_PLANE; i += 256) plane[i] = 0;
        }
    }

    float acc[2][8][4];
#pragma unroll
    for (int mi = 0; mi < 2; ++mi)
#pragma unroll
        for (int ni = 0; ni < 8; ++ni)
#pragma unroll
            for (int q = 0; q < 4; ++q) acc[mi][ni][q] = 0.0f;

    const int pix_base = (warp_m & 1) << 5;
    const int row_sel  = warp_m >> 1;
    const int co_st    = tid & 127;          // staging: cout handled by thread
    const int kg_st    = (tid >> 7) << 5;    // staging: k base (0 or 32)

    // ---- mainloop: 9 taps ----
#pragma unroll 1
    for (int t = 0; t < 9; ++t) {
        const int kh = (t >= 6) ? 2 : ((t >= 3) ? 1 : 0);
        const int kw = t - 3 * kh;

        // stage weight tap t: [cin 64][cout 128] -> Bs[cout][cin]
        // per thread: 32 coalesced LDG.32 along k, STS.128 conflict-free
        {
            const float* wsl = wt + (size_t)t * CIN * COUT + co_st;
#pragma unroll
            for (int hh = 0; hh < 2; ++hh) {
                float v[16];
#pragma unroll
                for (int j = 0; j < 16; ++j)
                    v[j] = wsl[(kg_st + hh * 16 + j) * COUT];
#pragma unroll
                for (int j4 = 0; j4 < 4; ++j4) {
                    uint4 tv;
                    tv.x = cvt_tf32(v[j4 * 4 + 0]);
                    tv.y = cvt_tf32(v[j4 * 4 + 1]);
                    tv.z = cvt_tf32(v[j4 * 4 + 2]);
                    tv.w = cvt_tf32(v[j4 * 4 + 3]);
                    *(uint4*)&Bs[co_st * BP + kg_st + hh * 16 + j4 * 4] = tv;
                }
            }
        }
        __syncthreads();

        const uint32_t* ap = As + (row_sel + kh) * A_PLANE
                              + (pix_base + gid + kw) * AP + t4;
        const uint32_t* bp = Bs + (warp_n * 64 + gid) * BP + t4;

#pragma unroll
        for (int ks = 0; ks < 8; ++ks) {
            const int cb = ks * 8;
            uint32_t a[2][4];
#pragma unroll
            for (int mi = 0; mi < 2; ++mi) {
                const uint32_t* p = ap + mi * 16 * AP + cb;
                a[mi][0] = p[0];
                a[mi][1] = p[8 * AP];
                a[mi][2] = p[4];
                a[mi][3] = p[8 * AP + 4];
            }
#pragma unroll
            for (int ni = 0; ni < 8; ++ni) {
                const uint32_t b0 = bp[ni * 8 * BP + cb];
                const uint32_t b1 = bp[ni * 8 * BP + cb + 4];
                MMA_TF32(acc[0][ni], a[0], b0, b1);
                MMA_TF32(acc[1][ni], a[1], b0, b1);
            }
        }
        __syncthreads();   // Bs consumed; safe to restage next tap
    }

    // ---- epilogue: bias + store ----
    const int hrow = h0 + row_sel;
    float* orow = out + ((size_t)n * CH + hrow) * CW * COUT + (size_t)ps * COUT;
    const int nb = warp_n * 64 + t4 * 2;

    float2 bv[8];
#pragma unroll
    for (int ni = 0; ni < 8; ++ni)
        bv[ni] = *(const float2*)&bias[nb + ni * 8];

#pragma unroll
    for (int mi = 0; mi < 2; ++mi) {
        const int p0 = pix_base + mi * 16 + gid;
#pragma unroll
        for (int ni = 0; ni < 8; ++ni) {
            const int cout = nb + ni * 8;
            float2 v0, v1;
            v0.x = acc[mi][ni][0] + bv[ni].x;
            v0.y = acc[mi][ni][1] + bv[ni].y;
            v1.x = acc[mi][ni][2] + bv[ni].x;
            v1.y = acc[mi][ni][3] + bv[ni].y;
            *(float2*)&orow[(size_t)p0 * COUT + cout]       = v0;
            *(float2*)&orow[(size_t)(p0 + 8) * COUT + cout] = v1;
        }
    }
}

extern "C" void kernel_launch(void* const* d_in, const int* in_sizes, int n_in,
                              void* d_out, int out_size) {
    const float* x    = (const float*)d_in[0];
    const float* wt   = (const float*)d_in[1];
    const float* bias = (const float*)d_in[2];
    float* out = (float*)d_out;

    cudaFuncSetAttribute(conv3x3_mma2_kernel,
                         cudaFuncAttributeMaxDynamicSharedMemorySize, SMEM_BYTES);

    const int nbatch = in_sizes[0] / (CH * CW * CIN);   // 16
    dim3 grid(nbatch * CH);                             // 2048 CTAs
    conv3x3_mma2_kernel<<<grid, 256, SMEM_BYTES>>>(x, wt, bias, out);
}

// round 5
// speedup vs baseline: 1.0570x; 1.0570x over previous
#include <cuda_runtime.h>
#include <cuda_fp16.h>
#include <cstdint>

// Conv2D 3x3 SAME stride-1 via mma.sync.m16n8k16.f16 (fp32 accum) implicit GEMM.
// x [16,128,128,64] NHWC fp32, w [3,3,64,128] HWIO, bias [128] -> out [16,128,128,128] fp32.
// fp16 has the same 11-bit mantissa as tf32; data range (|x|<~6, |w|<~0.3) is far
// inside fp16 range, accumulation in fp32 -> accuracy ~= tf32 path (~3e-4).
// CTA tile: M=128 (2 output rows x 64-pixel strip) x N=128 couts, 2 CTAs/SM.

#define CH 128
#define CW 128
#define CIN 64
#define COUT 128

#define APH 72                     // A row stride in halves (36 words): conflict-free
#define A_PLANE_H (66 * APH)       // 66 pixel rows (64 + 2 halo)
#define AS_HALVES (4 * A_PLANE_H)
#define BPH 72                     // B row stride in halves
#define BS_HALVES (COUT * BPH)
#define SMEM_BYTES ((AS_HALVES + BS_HALVES) * 2)   // 56,448 B

#define MMA_F16(c, a, b0, b1) \
    asm volatile("mma.sync.aligned.m16n8k16.row.col.f32.f16.f16.f32 " \
        "{%0,%1,%2,%3}, {%4,%5,%6,%7}, {%8,%9}, {%0,%1,%2,%3};" \
        : "+f"((c)[0]), "+f"((c)[1]), "+f"((c)[2]), "+f"((c)[3]) \
        : "r"((a)[0]), "r"((a)[1]), "r"((a)[2]), "r"((a)[3]), \
          "r"(b0), "r"(b1))

static __device__ __forceinline__ uint32_t pack2(float lo, float hi) {
    __half2 h = __floats2half2_rn(lo, hi);
    return *(uint32_t*)&h;
}

__global__ __launch_bounds__(256, 2)
void conv3x3_h16_kernel(const float* __restrict__ x,
                        const float* __restrict__ wt,
                        const float* __restrict__ bias,
                        float* __restrict__ out) {
    extern __shared__ uint32_t smem[];
    uint32_t* As = smem;                       // [plane 0..3][pixrow 0..65][cin], halves
    uint32_t* Bs = smem + AS_HALVES / 2;       // [cout][cin], halves

    const int tid  = threadIdx.x;
    const int wid  = tid >> 5;
    const int lane = tid & 31;
    const int gid  = lane >> 2;          // 0..7
    const int t4   = lane & 3;           // 0..3

    const int warp_m = wid >> 1;         // 0..3
    const int warp_n = wid & 1;          // 0..1

    const int bx = blockIdx.x;
    const int n  = bx >> 7;
    const int r  = bx & 127;
    const int h0 = (r >> 1) << 1;        // output rows h0, h0+1
    const int ps = (r & 1) << 6;         // pixel strip base: 0 or 64

    // ---- stage A: 4 input row planes (h0-1..h0+2), 66 pixels with halo, fp16 ----
    const float* xn = x + (size_t)n * CH * CW * CIN;
#pragma unroll
    for (int r4 = 0; r4 < 4; ++r4) {
        const int hr = h0 - 1 + r4;
        uint32_t* plane = As + r4 * (A_PLANE_H / 2);
        if ((unsigned)hr < (unsigned)CH) {
            const float* xrow = xn + (size_t)hr * CW * CIN;
#pragma unroll
            for (int i = 0; i < 3; ++i) {
                const int f8 = i * 256 + tid;            // uint4 = 8 halves each
                if (f8 < 66 * 8) {
                    const int pr = f8 >> 3;              // plane pixel row
                    const int c8 = (f8 & 7) << 3;        // cin base (8 per store)
                    const int gp = ps - 1 + pr;          // global pixel
                    uint4 tv = make_uint4(0u, 0u, 0u, 0u);
                    if ((unsigned)gp < (unsigned)CW) {
                        const float4 v0 = *(const float4*)&xrow[gp * CIN + c8];
                        const float4 v1 = *(const float4*)&xrow[gp * CIN + c8 + 4];
                        tv.x = pack2(v0.x, v0.y); tv.y = pack2(v0.z, v0.w);
                        tv.z = pack2(v1.x, v1.y); tv.w = pack2(v1.z, v1.w);
                    }
                    *(uint4*)&plane[(pr * APH + c8) >> 1] = tv;
                }
            }
        } else {
            for (int i = tid; i < A_PLANE_H / 2; i += 256) plane[i] = 0;
        }
    }

    float acc[2][8][4];
#pragma unroll
    for (int mi = 0; mi < 2; ++mi)
#pragma unroll
        for (int ni = 0; ni < 8; ++ni)
#pragma unroll
            for (int q = 0; q < 4; ++q) acc[mi][ni][q] = 0.0f;

    const int pix_base = (warp_m & 1) << 5;
    const int row_sel  = warp_m >> 1;
    const int co_st    = tid & 127;          // staging: cout handled by thread
    const int kg_st    = (tid >> 7) << 5;    // staging: k base in halves (0 or 32)

    // ---- mainloop: 9 taps ----
#pragma unroll 1
    for (int t = 0; t < 9; ++t) {
        const int kh = (t >= 6) ? 2 : ((t >= 3) ? 1 : 0);
        const int kw = t - 3 * kh;

        // stage weight tap t: [cin 64][cout 128] -> Bs[cout][cin] fp16
        {
            const float* wsl = wt + (size_t)t * CIN * COUT + co_st;
            float v[32];
#pragma unroll
            for (int j = 0; j < 32; ++j)
                v[j] = wsl[(kg_st + j) * COUT];
#pragma unroll
            for (int j4 = 0; j4 < 4; ++j4) {
                uint4 tv;
                tv.x = pack2(v[j4 * 8 + 0], v[j4 * 8 + 1]);
                tv.y = pack2(v[j4 * 8 + 2], v[j4 * 8 + 3]);
                tv.z = pack2(v[j4 * 8 + 4], v[j4 * 8 + 5]);
                tv.w = pack2(v[j4 * 8 + 6], v[j4 * 8 + 7]);
                *(uint4*)&Bs[(co_st * BPH + kg_st) / 2 + j4 * 4] = tv;
            }
        }
        __syncthreads();

        // fragment base pointers (word units; each word = 2 halves = 2 cin)
        const uint32_t* ap = As + (row_sel + kh) * (A_PLANE_H / 2)
                              + (pix_base + gid + kw) * (APH / 2) + t4;
        const uint32_t* bp = Bs + (warp_n * 64 + gid) * (BPH / 2) + t4;

#pragma unroll
        for (int ks = 0; ks < 4; ++ks) {       // 4 k16 steps over cin=64
            const int cb = ks * 8;             // word offset = 16 halves
            uint32_t a[2][4];
#pragma unroll
            for (int mi = 0; mi < 2; ++mi) {
                const uint32_t* p = ap + mi * 16 * (APH / 2) + cb;
                a[mi][0] = p[0];                    // (row,   k0..7)
                a[mi][1] = p[8 * (APH / 2)];        // (row+8, k0..7)
                a[mi][2] = p[4];                    // (row,   k8..15)
                a[mi][3] = p[8 * (APH / 2) + 4];    // (row+8, k8..15)
            }
#pragma unroll
            for (int ni = 0; ni < 8; ++ni) {
                const uint32_t b0 = bp[ni * 8 * (BPH / 2) + cb];
                const uint32_t b1 = bp[ni * 8 * (BPH / 2) + cb + 4];
                MMA_F16(acc[0][ni], a[0], b0, b1);
                MMA_F16(acc[1][ni], a[1], b0, b1);
            }
        }
        __syncthreads();   // Bs consumed; safe to restage next tap
    }

    // ---- epilogue: bias + store ----
    const int hrow = h0 + row_sel;
    float* orow = out + ((size_t)n * CH + hrow) * CW * COUT + (size_t)ps * COUT;
    const int nb = warp_n * 64 + t4 * 2;

    float2 bv[8];
#pragma unroll
    for (int ni = 0; ni < 8; ++ni)
        bv[ni] = *(const float2*)&bias[nb + ni * 8];

#pragma unroll
    for (int mi = 0; mi < 2; ++mi) {
        const int p0 = pix_base + mi * 16 + gid;
#pragma unroll
        for (int ni = 0; ni < 8; ++ni) {
            const int cout = nb + ni * 8;
            float2 v0, v1;
            v0.x = acc[mi][ni][0] + bv[ni].x;
            v0.y = acc[mi][ni][1] + bv[ni].y;
            v1.x = acc[mi][ni][2] + bv[ni].x;
            v1.y = acc[mi][ni][3] + bv[ni].y;
            *(float2*)&orow[(size_t)p0 * COUT + cout]       = v0;
            *(float2*)&orow[(size_t)(p0 + 8) * COUT + cout] = v1;
        }
    }
}

extern "C" void kernel_launch(void* const* d_in, const int* in_sizes, int n_in,
                              void* d_out, int out_size) {
    const float* x    = (const float*)d_in[0];
    const float* wt   = (const float*)d_in[1];
    const float* bias = (const float*)d_in[2];
    float* out = (float*)d_out;

    cudaFuncSetAttribute(conv3x3_h16_kernel,
                         cudaFuncAttributeMaxDynamicSharedMemorySize, SMEM_BYTES);

    const int nbatch = in_sizes[0] / (CH * CW * CIN);   // 16
    dim3 grid(nbatch * CH);                             // 2048 CTAs
    conv3x3_h16_kernel<<<grid, 256, SMEM_BYTES>>>(x, wt, bias, out);
}

// round 6
// speedup vs baseline: 1.7297x; 1.6364x over previous
#include <cuda_runtime.h>
#include <cuda_fp16.h>
#include <cstdint>

// Conv2D 3x3 SAME stride-1, mma.sync.m16n8k16.f16 (fp32 accum).
// Pipeline: (1) convert x -> fp16 gmem, (2) convert+transpose+swizzle w -> fp16
// gmem smem-image, (3) main kernel: stage A halo planes + ALL 9 weight taps into
// smem once via cp.async, then a sync-free pure LDS+MMA mainloop.
// CTA: M=256 (2 out rows x 128 pix) x N=128 couts, 512 thr, 16 warps of 64x32.

#define CH 128
#define CW 128
#define CIN 64
#define COUT 128
#define NTAP 9
#define NB 16                    // batch

#define X_ELEMS (NB*CH*CW*CIN)   // 16,777,216
#define W_WORDS (NTAP*COUT*32)   // 36,864 u32 (swizzled fp16 image)

__device__ __align__(16) __half    g_xh[X_ELEMS];
__device__ __align__(16) uint32_t  g_wh[W_WORDS];

// main-kernel smem (u32 words)
#define APW 36                   // A pixel-row stride in words (72 halves, 144B)
#define A_PLANE_W (130*APW)      // 4680 words/plane (130 pixel rows incl halo)
#define AS_WORDS (4*A_PLANE_W)   // 18,720
#define SMEM_WORDS (AS_WORDS + W_WORDS)
#define SMEM_BYTES (SMEM_WORDS*4)          // 222,336 B

#define MMA_F16(c, a, b0, b1) \
    asm volatile("mma.sync.aligned.m16n8k16.row.col.f32.f16.f16.f32 " \
        "{%0,%1,%2,%3}, {%4,%5,%6,%7}, {%8,%9}, {%0,%1,%2,%3};" \
        : "+f"((c)[0]), "+f"((c)[1]), "+f"((c)[2]), "+f"((c)[3]) \
        : "r"((a)[0]), "r"((a)[1]), "r"((a)[2]), "r"((a)[3]), \
          "r"(b0), "r"(b1))

static __device__ __forceinline__ uint32_t smem_u32(const void* p) {
    uint32_t a;
    asm("{ .reg .u64 t; cvta.to.shared.u64 t, %1; cvt.u32.u64 %0, t; }" : "=r"(a) : "l"(p));
    return a;
}
static __device__ __forceinline__ void cp16(uint32_t dst, const void* src, int sz) {
    asm volatile("cp.async.ca.shared.global [%0], [%1], 16, %2;"
                 :: "r"(dst), "l"(src), "r"(sz) : "memory");
}

// ---- pre-kernel 1: x fp32 -> fp16 ----
__global__ void cvt_x_kernel(const float* __restrict__ x) {
    const float4* x4 = (const float4*)x;
    uint2* d = (uint2*)g_xh;
    const int total = X_ELEMS / 4;
    for (int i = blockIdx.x * blockDim.x + threadIdx.x; i < total;
         i += gridDim.x * blockDim.x) {
        const float4 v = x4[i];
        const __half2 h0 = __floats2half2_rn(v.x, v.y);
        const __half2 h1 = __floats2half2_rn(v.z, v.w);
        uint2 o;
        o.x = *(const uint32_t*)&h0;
        o.y = *(const uint32_t*)&h1;
        d[i] = o;
    }
}

// ---- pre-kernel 2: w [tap][k][co] fp32 -> fp16 [tap][co][k], XOR-swizzled 16B chunks ----
__global__ void cvt_w_kernel(const float* __restrict__ wt) {
    const int tid = blockIdx.x * blockDim.x + threadIdx.x;   // = ((t*64+k)<<7)|co
    if (tid >= NTAP * CIN * COUT) return;
    const int co = tid & 127;
    const int k  = (tid >> 7) & 63;
    const int t  = tid >> 13;
    __half* dst = (__half*)g_wh;
    const int half_idx = (t * COUT + co) * 64 + (((k >> 3) ^ (co & 7)) << 3) + (k & 7);
    dst[half_idx] = __float2half(wt[tid]);
}

// ---- main kernel ----
__global__ __launch_bounds__(512, 1)
void conv3x3_h16s_kernel(const float* __restrict__ bias, float* __restrict__ out) {
    extern __shared__ uint32_t smem[];
    const uint32_t sb = smem_u32(smem);

    const int tid  = threadIdx.x;
    const int wid  = tid >> 5;
    const int lane = tid & 31;
    const int gid  = lane >> 2;
    const int t4   = lane & 3;
    const int warp_m = wid >> 2;         // 0..3
    const int warp_n = wid & 3;          // 0..3

    const int bx = blockIdx.x;
    const int n  = bx >> 6;
    const int h0 = (bx & 63) << 1;       // output rows h0, h0+1

    // ---- prologue: cp.async A (4 halo planes) + all 9 weight taps ----
    const __half* xn = g_xh + (size_t)n * CH * CW * CIN;
#pragma unroll
    for (int i = 0; i < 9; ++i) {
        const int c = tid + i * 512;               // 4160 chunks total
        if (c < 4160) {
            const int plane = c / 1040;            // 130 rows x 8 chunks
            const int rem   = c - plane * 1040;
            const int prow  = rem >> 3;
            const int c8    = rem & 7;
            const int hr = h0 - 1 + plane;
            const int gp = prow - 1;
            const bool ok = ((unsigned)hr < (unsigned)CH) && ((unsigned)gp < (unsigned)CW);
            const __half* src = xn + ((size_t)(ok ? hr : 0) * CW + (ok ? gp : 0)) * CIN + c8 * 8;
            const uint32_t dst = sb + (plane * A_PLANE_W + prow * APW + c8 * 4) * 4;
            cp16(dst, src, ok ? 16 : 0);
        }
    }
#pragma unroll
    for (int i = 0; i < 18; ++i) {                 // 9216 chunks, contiguous
        const int c = tid + i * 512;
        cp16(sb + (AS_WORDS + c * 4) * 4, g_wh + c * 4, 16);
    }
    asm volatile("cp.async.commit_group;");
    asm volatile("cp.async.wait_group 0;" ::: "memory");
    __syncthreads();

    // ---- mainloop: 9 taps x 4 k16-steps, no syncs, no gmem ----
    float acc[4][4][4];
#pragma unroll
    for (int mi = 0; mi < 4; ++mi)
#pragma unroll
        for (int ni = 0; ni < 4; ++ni)
#pragma unroll
            for (int q = 0; q < 4; ++q) acc[mi][ni][q] = 0.0f;

    const int row_sel  = warp_m >> 1;
    const int pix_base = (warp_m & 1) << 6;

#pragma unroll 1
    for (int t = 0; t < 9; ++t) {
        const int kh = (t * 11) >> 5;              // t/3
        const int kw = t - kh * 3;
        const uint32_t* abase = smem + (row_sel + kh) * A_PLANE_W
                                + (pix_base + gid + kw) * APW + t4;
        const uint32_t* bbase = smem + AS_WORDS + (t * COUT) * 32 + t4;

#pragma unroll
        for (int ks = 0; ks < 4; ++ks) {
            uint32_t a[4][4];
#pragma unroll
            for (int mi = 0; mi < 4; ++mi) {
                const uint32_t* p = abase + mi * 16 * APW + ks * 8;
                a[mi][0] = p[0];
                a[mi][1] = p[8 * APW];
                a[mi][2] = p[4];
                a[mi][3] = p[8 * APW + 4];
            }
            uint32_t b[4][2];
#pragma unroll
            for (int ni = 0; ni < 4; ++ni) {
                const int co = warp_n * 32 + ni * 8 + gid;    // co&7 == gid
                const uint32_t* q = bbase + co * 32;
                b[ni][0] = q[(((ks * 2)     ^ gid) << 2)];
                b[ni][1] = q[(((ks * 2 + 1) ^ gid) << 2)];
            }
#pragma unroll
            for (int mi = 0; mi < 4; ++mi)
#pragma unroll
                for (int ni = 0; ni < 4; ++ni)
                    MMA_F16(acc[mi][ni], a[mi], b[ni][0], b[ni][1]);
        }
    }

    // ---- epilogue: bias + store ----
    const int hrow = h0 + row_sel;
    float* orow = out + ((size_t)n * CH + hrow) * CW * COUT;
    const int co0 = warp_n * 32 + t4 * 2;

    float2 bv[4];
#pragma unroll
    for (int ni = 0; ni < 4; ++ni)
        bv[ni] = *(const float2*)&bias[co0 + ni * 8];

#pragma unroll
    for (int mi = 0; mi < 4; ++mi) {
        const int p0 = pix_base + mi * 16 + gid;
#pragma unroll
        for (int ni = 0; ni < 4; ++ni) {
            const int cout = co0 + ni * 8;
            float2 v0, v1;
            v0.x = acc[mi][ni][0] + bv[ni].x;
            v0.y = acc[mi][ni][1] + bv[ni].y;
            v1.x = acc[mi][ni][2] + bv[ni].x;
            v1.y = acc[mi][ni][3] + bv[ni].y;
            *(float2*)&orow[(size_t)p0 * COUT + cout]       = v0;
            *(float2*)&orow[(size_t)(p0 + 8) * COUT + cout] = v1;
        }
    }
}

extern "C" void kernel_launch(void* const* d_in, const int* in_sizes, int n_in,
                              void* d_out, int out_size) {
    const float* x    = (const float*)d_in[0];
    const float* wt   = (const float*)d_in[1];
    const float* bias = (const float*)d_in[2];
    float* out = (float*)d_out;

    cudaFuncSetAttribute(conv3x3_h16s_kernel,
                         cudaFuncAttributeMaxDynamicSharedMemorySize, SMEM_BYTES);

    cvt_x_kernel<<<4096, 256>>>(x);
    cvt_w_kernel<<<(NTAP * CIN * COUT + 255) / 256, 256>>>(wt);

    dim3 grid(NB * (CH / 2));                      // 1024 CTAs
    conv3x3_h16s_kernel<<<grid, 512, SMEM_BYTES>>>(bias, out);
}

// round 7
// speedup vs baseline: 1.7417x; 1.0070x over previous
#include <cuda_runtime.h>
#include <cuda_fp16.h>
#include <cstdint>

// Conv2D 3x3 SAME stride-1, mma.sync.m16n8k16.f16 (fp32 accum).
// (1) cvt x -> fp16 gmem (MLP-4), (2) cvt+transpose+swizzle w -> fp16 smem-image,
// (3) main: cp.async stage (A planes + 9 taps, 3 pipelined groups), then
// ldmatrix + MMA mainloop (6 LDSM + 16 MMA per k-step), no gmem, 3 syncs total.
// CTA: M=256 (2 out rows x 128 pix) x N=128 couts, 512 thr, 16 warps of 64x32.

#define CH 128
#define CW 128
#define CIN 64
#define COUT 128
#define NTAP 9
#define NB 16

#define X_ELEMS (NB*CH*CW*CIN)
#define W_WORDS (NTAP*COUT*32)

__device__ __align__(16) __half    g_xh[X_ELEMS];
__device__ __align__(16) uint32_t  g_wh[W_WORDS];

#define APW 36                   // A pixel-row stride in words (144 B)
#define A_PLANE_W (130*APW)
#define AS_WORDS (4*A_PLANE_W)
#define SMEM_WORDS (AS_WORDS + W_WORDS)
#define SMEM_BYTES (SMEM_WORDS*4)          // 222,336 B

#define MMA_F16(c, a, b0, b1) \
    asm volatile("mma.sync.aligned.m16n8k16.row.col.f32.f16.f16.f32 " \
        "{%0,%1,%2,%3}, {%4,%5,%6,%7}, {%8,%9}, {%0,%1,%2,%3};" \
        : "+f"((c)[0]), "+f"((c)[1]), "+f"((c)[2]), "+f"((c)[3]) \
        : "r"((a)[0]), "r"((a)[1]), "r"((a)[2]), "r"((a)[3]), \
          "r"(b0), "r"(b1))

#define LDSM4(r0, r1, r2, r3, addr) \
    asm volatile("ldmatrix.sync.aligned.m8n8.x4.shared.b16 {%0,%1,%2,%3}, [%4];" \
        : "=r"(r0), "=r"(r1), "=r"(r2), "=r"(r3) : "r"(addr))

static __device__ __forceinline__ uint32_t smem_u32(const void* p) {
    uint32_t a;
    asm("{ .reg .u64 t; cvta.to.shared.u64 t, %1; cvt.u32.u64 %0, t; }" : "=r"(a) : "l"(p));
    return a;
}
static __device__ __forceinline__ void cp16(uint32_t dst, const void* src, int sz) {
    asm volatile("cp.async.ca.shared.global [%0], [%1], 16, %2;"
                 :: "r"(dst), "l"(src), "r"(sz) : "memory");
}

// ---- pre-kernel 1: x fp32 -> fp16 (4 independent loads per thread) ----
__global__ void cvt_x_kernel(const float* __restrict__ x) {
    const float4* x4 = (const float4*)x;
    uint2* d = (uint2*)g_xh;
    const int i = blockIdx.x * 256 + threadIdx.x;
    const int stride = 4096 * 256;               // X_ELEMS/4 == 4*stride
    float4 v0 = x4[i];
    float4 v1 = x4[i + stride];
    float4 v2 = x4[i + 2 * stride];
    float4 v3 = x4[i + 3 * stride];
    __half2 h;
    uint2 o;
#define PK(v, idx) \
    h = __floats2half2_rn((v).x, (v).y); o.x = *(const uint32_t*)&h; \
    h = __floats2half2_rn((v).z, (v).w); o.y = *(const uint32_t*)&h; \
    d[idx] = o;
    PK(v0, i) PK(v1, i + stride) PK(v2, i + 2 * stride) PK(v3, i + 3 * stride)
#undef PK
}

// ---- pre-kernel 2: w [tap][k][co] -> fp16 [tap][co][k], XOR-swizzled 16B chunks ----
__global__ void cvt_w_kernel(const float* __restrict__ wt) {
    const int tid = blockIdx.x * blockDim.x + threadIdx.x;
    if (tid >= NTAP * CIN * COUT) return;
    const int co = tid & 127;
    const int k  = (tid >> 7) & 63;
    const int t  = tid >> 13;
    __half* dst = (__half*)g_wh;
    const int half_idx = (t * COUT + co) * 64 + (((k >> 3) ^ (co & 7)) << 3) + (k & 7);
    dst[half_idx] = __float2half(wt[tid]);
}

// ---- main kernel ----
__global__ __launch_bounds__(512, 1)
void conv3x3_h16l_kernel(const float* __restrict__ bias, float* __restrict__ out) {
    extern __shared__ uint32_t smem[];
    const uint32_t sb = smem_u32(smem);
    const uint32_t sbB = sb + AS_WORDS * 4;

    const int tid  = threadIdx.x;
    const int wid  = tid >> 5;
    const int lane = tid & 31;
    const int gid  = lane >> 2;
    const int t4   = lane & 3;
    const int warp_m = wid >> 2;
    const int warp_n = wid & 3;

    const int bx = blockIdx.x;
    const int n  = bx >> 6;
    const int h0 = (bx & 63) << 1;

    // ---- prologue: cp.async A planes + taps 0-2 | taps 3-5 | taps 6-8 ----
    const __half* xn = g_xh + (size_t)n * CH * CW * CIN;
#pragma unroll
    for (int i = 0; i < 9; ++i) {
        const int c = tid + i * 512;               // 4160 A chunks
        if (c < 4160) {
            const int plane = c / 1040;
            const int rem   = c - plane * 1040;
            const int prow  = rem >> 3;
            const int c8    = rem & 7;
            const int hr = h0 - 1 + plane;
            const int gp = prow - 1;
            const bool ok = ((unsigned)hr < (unsigned)CH) && ((unsigned)gp < (unsigned)CW);
            const __half* src = xn + ((size_t)(ok ? hr : 0) * CW + (ok ? gp : 0)) * CIN + c8 * 8;
            cp16(sb + (plane * A_PLANE_W + prow * APW + c8 * 4) * 4, src, ok ? 16 : 0);
        }
    }
#pragma unroll
    for (int i = 0; i < 6; ++i) {                  // taps 0-2
        const int c = tid + i * 512;
        cp16(sbB + c * 16, g_wh + c * 4, 16);
    }
    asm volatile("cp.async.commit_group;");
#pragma unroll
    for (int i = 6; i < 12; ++i) {                 // taps 3-5
        const int c = tid + i * 512;
        cp16(sbB + c * 16, g_wh + c * 4, 16);
    }
    asm volatile("cp.async.commit_group;");
#pragma unroll
    for (int i = 12; i < 18; ++i) {                // taps 6-8
        const int c = tid + i * 512;
        cp16(sbB + c * 16, g_wh + c * 4, 16);
    }
    asm volatile("cp.async.commit_group;");

    // ---- mainloop ----
    float acc[4][4][4];
#pragma unroll
    for (int mi = 0; mi < 4; ++mi)
#pragma unroll
        for (int ni = 0; ni < 4; ++ni)
#pragma unroll
            for (int q = 0; q < 4; ++q) acc[mi][ni][q] = 0.0f;

    const int row_sel  = warp_m >> 1;
    const int pix_base = (warp_m & 1) << 6;

    // per-lane ldmatrix offsets
    const uint32_t lane_off_a = (uint32_t)((lane & 15) * 144 + (lane >> 4) * 16);
    const int xlane   = lane & 7;
    const int kbit    = (lane >> 3) & 1;
    const int co_lane = xlane + ((lane >> 4) << 3);
    const uint32_t bco = (uint32_t)((warp_n * 32 + co_lane) * 128);

#pragma unroll 1
    for (int t = 0; t < 9; ++t) {
        if (t == 0) { asm volatile("cp.async.wait_group 2;" ::: "memory"); __syncthreads(); }
        else if (t == 3) { asm volatile("cp.async.wait_group 1;" ::: "memory"); __syncthreads(); }
        else if (t == 6) { asm volatile("cp.async.wait_group 0;" ::: "memory"); __syncthreads(); }

        const int kh = (t * 11) >> 5;
        const int kw = t - kh * 3;
        const uint32_t abase = sb + (uint32_t)((row_sel + kh) * (A_PLANE_W * 4)
                                   + (pix_base + kw) * 144) + lane_off_a;
        const uint32_t bbase0 = sbB + (uint32_t)t * 16384u + bco;
        const uint32_t bbase1 = bbase0 + 2048u;

#pragma unroll
        for (int ks = 0; ks < 4; ++ks) {
            uint32_t a[4][4];
#pragma unroll
            for (int mi = 0; mi < 4; ++mi)
                LDSM4(a[mi][0], a[mi][1], a[mi][2], a[mi][3],
                      abase + (uint32_t)(mi * 2304 + ks * 32));
            const uint32_t swz = (uint32_t)(((2 * ks + kbit) ^ xlane) << 4);
            uint32_t b0, b1, b2, b3, c0, c1, c2, c3;
            LDSM4(b0, b1, b2, b3, bbase0 + swz);
            LDSM4(c0, c1, c2, c3, bbase1 + swz);
#pragma unroll
            for (int mi = 0; mi < 4; ++mi) {
                MMA_F16(acc[mi][0], a[mi], b0, b1);
                MMA_F16(acc[mi][1], a[mi], b2, b3);
                MMA_F16(acc[mi][2], a[mi], c0, c1);
                MMA_F16(acc[mi][3], a[mi], c2, c3);
            }
        }
    }

    // ---- epilogue: bias + store ----
    const int hrow = h0 + row_sel;
    float* orow = out + ((size_t)n * CH + hrow) * CW * COUT;
    const int co0 = warp_n * 32 + t4 * 2;

    float2 bv[4];
#pragma unroll
    for (int ni = 0; ni < 4; ++ni)
        bv[ni] = *(const float2*)&bias[co0 + ni * 8];

#pragma unroll
    for (int mi = 0; mi < 4; ++mi) {
        const int p0 = pix_base + mi * 16 + gid;
#pragma unroll
        for (int ni = 0; ni < 4; ++ni) {
            const int cout = co0 + ni * 8;
            float2 v0, v1;
            v0.x = acc[mi][ni][0] + bv[ni].x;
            v0.y = acc[mi][ni][1] + bv[ni].y;
            v1.x = acc[mi][ni][2] + bv[ni].x;
            v1.y = acc[mi][ni][3] + bv[ni].y;
            *(float2*)&orow[(size_t)p0 * COUT + cout]       = v0;
            *(float2*)&orow[(size_t)(p0 + 8) * COUT + cout] = v1;
        }
    }
}

extern "C" void kernel_launch(void* const* d_in, const int* in_sizes, int n_in,
                              void* d_out, int out_size) {
    const float* x    = (const float*)d_in[0];
    const float* wt   = (const float*)d_in[1];
    const float* bias = (const float*)d_in[2];
    float* out = (float*)d_out;

    cudaFuncSetAttribute(conv3x3_h16l_kernel,
                         cudaFuncAttributeMaxDynamicSharedMemorySize, SMEM_BYTES);

    cvt_x_kernel<<<4096, 256>>>(x);
    cvt_w_kernel<<<(NTAP * CIN * COUT + 255) / 256, 256>>>(wt);

    dim3 grid(NB * (CH / 2));                      // 1024 CTAs
    conv3x3_h16l_kernel<<<grid, 512, SMEM_BYTES>>>(bias, out);
}

// round 8
// speedup vs baseline: 1.8237x; 1.0471x over previous
#include <cuda_runtime.h>
#include <cuda_fp16.h>
#include <cstdint>

// Conv2D 3x3 SAME stride-1, mma.sync.m16n8k16.f16 (fp32 accum).
// (1) cvt x -> fp16 gmem, (2) cvt+transpose+swizzle w -> fp16 smem-image,
// (3) main: A planes resident, B double-buffered per tap via cp.async from the
//     pre-swizzled image; ldmatrix + MMA mainloop. 70.8 KB smem -> 2 CTAs/SM so
//     prologue/tap-wait/epilogue of one CTA hides under the peer's HMMAs.
// CTA: M=128 (2 out rows x 64-pix strip) x N=128, 256 thr, 8 warps of 32x64.

#define CH 128
#define CW 128
#define CIN 64
#define COUT 128
#define NTAP 9
#define NB 16

#define X_ELEMS (NB*CH*CW*CIN)
#define W_WORDS (NTAP*COUT*32)

__device__ __align__(16) __half    g_xh[X_ELEMS];
__device__ __align__(16) uint32_t  g_wh[W_WORDS];

#define APW 36                       // A pixel-row stride in words (144 B)
#define A_PLANE_W (66*APW)           // 66 pixel rows (64 strip + 2 halo)
#define AS_WORDS (4*A_PLANE_W)       // 9504 words
#define B_BYTES 16384                // one tap image
#define SMEM_BYTES (AS_WORDS*4 + 2*B_BYTES)   // 70,784 B -> 2 CTAs/SM

#define MMA_F16(c, a, b0, b1) \
    asm volatile("mma.sync.aligned.m16n8k16.row.col.f32.f16.f16.f32 " \
        "{%0,%1,%2,%3}, {%4,%5,%6,%7}, {%8,%9}, {%0,%1,%2,%3};" \
        : "+f"((c)[0]), "+f"((c)[1]), "+f"((c)[2]), "+f"((c)[3]) \
        : "r"((a)[0]), "r"((a)[1]), "r"((a)[2]), "r"((a)[3]), \
          "r"(b0), "r"(b1))

#define LDSM4(r0, r1, r2, r3, addr) \
    asm volatile("ldmatrix.sync.aligned.m8n8.x4.shared.b16 {%0,%1,%2,%3}, [%4];" \
        : "=r"(r0), "=r"(r1), "=r"(r2), "=r"(r3) : "r"(addr))

static __device__ __forceinline__ uint32_t smem_u32(const void* p) {
    uint32_t a;
    asm("{ .reg .u64 t; cvta.to.shared.u64 t, %1; cvt.u32.u64 %0, t; }" : "=r"(a) : "l"(p));
    return a;
}
static __device__ __forceinline__ void cp16(uint32_t dst, const void* src, int sz) {
    asm volatile("cp.async.ca.shared.global [%0], [%1], 16, %2;"
                 :: "r"(dst), "l"(src), "r"(sz) : "memory");
}

// ---- pre-kernel 1: x fp32 -> fp16 (4 independent loads per thread) ----
__global__ void cvt_x_kernel(const float* __restrict__ x) {
    const float4* x4 = (const float4*)x;
    uint2* d = (uint2*)g_xh;
    const int i = blockIdx.x * 256 + threadIdx.x;
    const int stride = 4096 * 256;
    float4 v0 = x4[i];
    float4 v1 = x4[i + stride];
    float4 v2 = x4[i + 2 * stride];
    float4 v3 = x4[i + 3 * stride];
    __half2 h;
    uint2 o;
#define PK(v, idx) \
    h = __floats2half2_rn((v).x, (v).y); o.x = *(const uint32_t*)&h; \
    h = __floats2half2_rn((v).z, (v).w); o.y = *(const uint32_t*)&h; \
    d[idx] = o;
    PK(v0, i) PK(v1, i + stride) PK(v2, i + 2 * stride) PK(v3, i + 3 * stride)
#undef PK
}

// ---- pre-kernel 2: w [tap][k][co] -> fp16 [tap][co][k], XOR-swizzled 16B chunks ----
__global__ void cvt_w_kernel(const float* __restrict__ wt) {
    const int tid = blockIdx.x * blockDim.x + threadIdx.x;
    if (tid >= NTAP * CIN * COUT) return;
    const int co = tid & 127;
    const int k  = (tid >> 7) & 63;
    const int t  = tid >> 13;
    __half* dst = (__half*)g_wh;
    const int half_idx = (t * COUT + co) * 64 + (((k >> 3) ^ (co & 7)) << 3) + (k & 7);
    dst[half_idx] = __float2half(wt[tid]);
}

// ---- main kernel ----
__global__ __launch_bounds__(256, 2)
void conv3x3_db_kernel(const float* __restrict__ bias, float* __restrict__ out) {
    extern __shared__ uint32_t smem[];
    const uint32_t sb  = smem_u32(smem);
    const uint32_t sbB = sb + AS_WORDS * 4;

    const int tid  = threadIdx.x;
    const int wid  = tid >> 5;
    const int lane = tid & 31;
    const int gid  = lane >> 2;
    const int t4   = lane & 3;
    const int warp_m = wid >> 1;         // 0..3
    const int warp_n = wid & 1;          // 0..1

    const int bx = blockIdx.x;
    const int n  = bx >> 7;
    const int r  = bx & 127;
    const int h0 = (r >> 1) << 1;        // output rows h0, h0+1
    const int ps = (r & 1) << 6;         // pixel strip base: 0 or 64

    // ---- prologue: cp.async A (4 halo planes, 2112 chunks) + B tap 0 ----
    const __half* xn = g_xh + (size_t)n * CH * CW * CIN;
#pragma unroll
    for (int i = 0; i < 9; ++i) {
        const int c = tid + i * 256;
        if (c < 2112) {
            const int plane = c / 528;           // 66 rows x 8 chunks
            const int rem   = c - plane * 528;
            const int prow  = rem >> 3;
            const int c8    = rem & 7;
            const int hr = h0 - 1 + plane;
            const int gp = ps - 1 + prow;
            const bool ok = ((unsigned)hr < (unsigned)CH) && ((unsigned)gp < (unsigned)CW);
            const __half* src = xn + ((size_t)(ok ? hr : 0) * CW + (ok ? gp : 0)) * CIN + c8 * 8;
            cp16(sb + (plane * A_PLANE_W + prow * APW) * 4 + c8 * 16, src, ok ? 16 : 0);
        }
    }
#pragma unroll
    for (int i = 0; i < 4; ++i) {                // B tap 0: 1024 chunks
        const int c = tid + i * 256;
        cp16(sbB + c * 16, g_wh + c * 4, 16);
    }
    asm volatile("cp.async.commit_group;");

    // ---- accumulators ----
    float acc[2][8][4];
#pragma unroll
    for (int mi = 0; mi < 2; ++mi)
#pragma unroll
        for (int ni = 0; ni < 8; ++ni)
#pragma unroll
            for (int q = 0; q < 4; ++q) acc[mi][ni][q] = 0.0f;

    const int row_sel  = warp_m >> 1;
    const int pix_base = (warp_m & 1) << 5;

    const uint32_t lane_off_a = (uint32_t)((lane & 15) * 144 + (lane >> 4) * 16);
    const int xlane   = lane & 7;
    const int kbit    = (lane >> 3) & 1;
    const int co_lane = xlane + ((lane >> 4) << 3);
    const uint32_t bco = (uint32_t)((warp_n * 64 + co_lane) * 128);

    // ---- mainloop: 9 taps, B double-buffered ----
#pragma unroll 1
    for (int t = 0; t < 9; ++t) {
        asm volatile("cp.async.wait_group 0;" ::: "memory");
        __syncthreads();    // B[t] visible to all warps; buf[(t+1)&1] free

        if (t < 8) {        // stage next tap, overlapped with this tap's MMAs
            const uint32_t dst = sbB + (uint32_t)(((t + 1) & 1) * B_BYTES);
            const uint32_t* src = g_wh + (t + 1) * 4096;
#pragma unroll
            for (int i = 0; i < 4; ++i) {
                const int c = tid + i * 256;
                cp16(dst + c * 16, src + c * 4, 16);
            }
            asm volatile("cp.async.commit_group;");
        }

        const int kh = (t * 11) >> 5;            // t/3
        const int kw = t - kh * 3;
        const uint32_t abase = sb + (uint32_t)((row_sel + kh) * (A_PLANE_W * 4)
                                   + (pix_base + kw) * 144) + lane_off_a;
        const uint32_t bb = sbB + (uint32_t)((t & 1) * B_BYTES) + bco;

#pragma unroll
        for (int ks = 0; ks < 4; ++ks) {
            uint32_t a[2][4];
#pragma unroll
            for (int mi = 0; mi < 2; ++mi)
                LDSM4(a[mi][0], a[mi][1], a[mi][2], a[mi][3],
                      abase + (uint32_t)(mi * 2304 + ks * 32));
            const uint32_t swz = (uint32_t)(((2 * ks + kbit) ^ xlane) << 4);
            uint32_t b[8];
            LDSM4(b[0], b[1], b[2], b[3], bb + swz);
            LDSM4(b[4], b[5], b[6], b[7], bb + 2048u + swz);
            uint32_t c[8];
            LDSM4(c[0], c[1], c[2], c[3], bb + 4096u + swz);
            LDSM4(c[4], c[5], c[6], c[7], bb + 6144u + swz);
#pragma unroll
            for (int mi = 0; mi < 2; ++mi) {
                MMA_F16(acc[mi][0], a[mi], b[0], b[1]);
                MMA_F16(acc[mi][1], a[mi], b[2], b[3]);
                MMA_F16(acc[mi][2], a[mi], b[4], b[5]);
                MMA_F16(acc[mi][3], a[mi], b[6], b[7]);
                MMA_F16(acc[mi][4], a[mi], c[0], c[1]);
                MMA_F16(acc[mi][5], a[mi], c[2], c[3]);
                MMA_F16(acc[mi][6], a[mi], c[4], c[5]);
                MMA_F16(acc[mi][7], a[mi], c[6], c[7]);
            }
        }
    }

    // ---- epilogue: bias + store ----
    const int hrow = h0 + row_sel;
    float* orow = out + (((size_t)n * CH + hrow) * CW + ps) * COUT;
    const int co0 = warp_n * 64 + t4 * 2;

    float2 bv[8];
#pragma unroll
    for (int ni = 0; ni < 8; ++ni)
        bv[ni] = *(const float2*)&bias[co0 + ni * 8];

#pragma unroll
    for (int mi = 0; mi < 2; ++mi) {
        const int p0 = pix_base + mi * 16 + gid;
#pragma unroll
        for (int ni = 0; ni < 8; ++ni) {
            const int cout = co0 + ni * 8;
            float2 v0, v1;
            v0.x = acc[mi][ni][0] + bv[ni].x;
            v0.y = acc[mi][ni][1] + bv[ni].y;
            v1.x = acc[mi][ni][2] + bv[ni].x;
            v1.y = acc[mi][ni][3] + bv[ni].y;
            *(float2*)&orow[(size_t)p0 * COUT + cout]       = v0;
            *(float2*)&orow[(size_t)(p0 + 8) * COUT + cout] = v1;
        }
    }
}

extern "C" void kernel_launch(void* const* d_in, const int* in_sizes, int n_in,
                              void* d_out, int out_size) {
    const float* x    = (const float*)d_in[0];
    const float* wt   = (const float*)d_in[1];
    const float* bias = (const float*)d_in[2];
    float* out = (float*)d_out;

    cudaFuncSetAttribute(conv3x3_db_kernel,
                         cudaFuncAttributeMaxDynamicSharedMemorySize, SMEM_BYTES);

    cvt_x_kernel<<<4096, 256>>>(x);
    cvt_w_kernel<<<(NTAP * CIN * COUT + 255) / 256, 256>>>(wt);

    dim3 grid(NB * CH);                          // 2048 CTAs
    conv3x3_db_kernel<<<grid, 256, SMEM_BYTES>>>(bias, out);
}